// round 3
// baseline (speedup 1.0000x reference)
#include <cuda_runtime.h>
#include <cuda_bf16.h>
#include <math.h>

// Problem constants
#define D512 512
#define T256 256
#define NROWS 2048          // T * TOPK
#define MAXH 2560
#define NEXP 16
#define NCLS 4096
#define TOPK 8

// ---------------- scratch (device globals; no allocation allowed) ----------
__device__ float g_h1[T256 * D512];
__device__ float g_h2[T256 * 256];
__device__ float g_scores[T256 * NCLS];
__device__ float g_lin[NROWS * D512];      // pre linear, later reused for post linear
__device__ float g_xin[NROWS * D512];      // pre output after LN+act
__device__ float g_hid[NROWS * MAXH];      // mlp hidden
__device__ float g_mlpout[NROWS * D512];
__device__ float g_z[NROWS * D512];        // post output (after optional LN)
__device__ int   g_preE[NROWS];
__device__ int   g_mlpE[NROWS];
__device__ int   g_postE[NROWS];
__device__ float g_wgt[NROWS];
__device__ int   g_cnt[48];
__device__ int   g_cur[48];
__device__ int   g_off[51];                // 3 x 17
__device__ int   g_permP[NROWS];
__device__ int   g_permM[NROWS];
__device__ int   g_permQ[NROWS];

// ---------------- activations ----------------
__device__ __forceinline__ float act_apply(int a, float v) {
    switch (a & 3) {
        case 0:  return 0.5f * v * (1.0f + erff(v * 0.70710678118654752f)); // exact gelu
        case 1:  return fmaxf(v, 0.0f);                                      // relu
        case 2:  return tanhf(v);                                            // tanh
        default: return v * (1.0f / (1.0f + expf(-v)));                      // silu
    }
}

// ---------------- generic (grouped) SGEMM ----------------
// Y[row, n] = epi( sum_k X[xrow(row), k] * W[e][k, n] + bias[e][n] )
// perm != null: rows taken from perm[segoff[e] .. segoff[e+1]) ; else rows 0..M-1, e = 0.
// ACT: 0 none, 1 gelu, 2 act by (e & 3)
// NKMODE: 0 none, 1 skip col-blocks with n0 >= he(e), 2 Keff = he(e)
#define BM 32
#define BN 128
#define BK 16

template<int ACT, int NKMODE>
__global__ __launch_bounds__(256)
void gemm_k(const float* __restrict__ X, int ldx, int xshift,
            const float* __restrict__ W, long wstride, int ldw,
            const float* __restrict__ bias, int bstride,
            float* __restrict__ Y, int ldy,
            int M, int K,
            const int* __restrict__ perm, const int* __restrict__ segoff)
{
    int e  = blockIdx.z;
    int n0 = blockIdx.x * BN;
    int he = 512 * (2 + (e >> 2));
    if (NKMODE == 1 && n0 >= he) return;
    int Keff = (NKMODE == 2) ? he : K;

    int segs, sege;
    if (perm) { segs = segoff[e]; sege = segoff[e + 1]; }
    else      { segs = 0;         sege = M; }
    int m0 = segs + blockIdx.y * BM;
    if (m0 >= sege) return;

    __shared__ float Xs[BK][BM];
    __shared__ float Ws[BK][BN];
    __shared__ int   rows[BM];

    int tid = threadIdx.x;
    if (tid < BM) {
        int p = m0 + tid;
        rows[tid] = (p < sege) ? (perm ? perm[p] : p) : -1;
    }
    __syncthreads();

    const float* Wb = W + (long)e * wstride;
    int tx = tid & 31, ty = tid >> 5;
    int c0 = tx * 4, r0 = ty * 4;

    float acc[4][4];
#pragma unroll
    for (int i = 0; i < 4; i++)
#pragma unroll
        for (int j = 0; j < 4; j++) acc[i][j] = 0.0f;

    int xm = tid >> 2, xk = (tid & 3) * 4;
    int xr = (tid < 128) ? rows[xm] : -1;
    const float* xp = (xr >= 0) ? (X + (long)(xr >> xshift) * ldx) : X;

    for (int k0 = 0; k0 < Keff; k0 += BK) {
        const float* wp = Wb + (long)(k0 + ty) * ldw + n0 + c0;
        float4 w0 = *(const float4*)wp;
        float4 w1 = *(const float4*)(wp + (long)8 * ldw);
        float4 xv = make_float4(0.f, 0.f, 0.f, 0.f);
        if (tid < 128 && xr >= 0) xv = *(const float4*)(xp + k0 + xk);

        *(float4*)&Ws[ty][c0]     = w0;
        *(float4*)&Ws[ty + 8][c0] = w1;
        if (tid < 128) {
            Xs[xk + 0][xm] = xv.x; Xs[xk + 1][xm] = xv.y;
            Xs[xk + 2][xm] = xv.z; Xs[xk + 3][xm] = xv.w;
        }
        __syncthreads();

#pragma unroll
        for (int kk = 0; kk < BK; kk++) {
            float4 a = *(const float4*)&Xs[kk][r0];
            float4 b = *(const float4*)&Ws[kk][c0];
            acc[0][0] += a.x * b.x; acc[0][1] += a.x * b.y; acc[0][2] += a.x * b.z; acc[0][3] += a.x * b.w;
            acc[1][0] += a.y * b.x; acc[1][1] += a.y * b.y; acc[1][2] += a.y * b.z; acc[1][3] += a.y * b.w;
            acc[2][0] += a.z * b.x; acc[2][1] += a.z * b.y; acc[2][2] += a.z * b.z; acc[2][3] += a.z * b.w;
            acc[3][0] += a.w * b.x; acc[3][1] += a.w * b.y; acc[3][2] += a.w * b.z; acc[3][3] += a.w * b.w;
        }
        __syncthreads();
    }

    float4 bb = *(const float4*)(bias + (long)e * bstride + n0 + c0);
#pragma unroll
    for (int i = 0; i < 4; i++) {
        int r = rows[r0 + i];
        if (r < 0) continue;
        float4 o;
        o.x = acc[i][0] + bb.x; o.y = acc[i][1] + bb.y;
        o.z = acc[i][2] + bb.z; o.w = acc[i][3] + bb.w;
        if (ACT == 1) {
            o.x = act_apply(0, o.x); o.y = act_apply(0, o.y);
            o.z = act_apply(0, o.z); o.w = act_apply(0, o.w);
        } else if (ACT == 2) {
            o.x = act_apply(e, o.x); o.y = act_apply(e, o.y);
            o.z = act_apply(e, o.z); o.w = act_apply(e, o.w);
        }
        *(float4*)(Y + (long)r * ldy + n0 + c0) = o;
    }
}

// ---------------- softmax + top-8 + route decompose ----------------
__global__ __launch_bounds__(256)
void topk_k(const float* __restrict__ scores, const float* __restrict__ temp,
            int* __restrict__ preE, int* __restrict__ mlpE, int* __restrict__ postE,
            float* __restrict__ wgt, int* __restrict__ cnt)
{
    int t = blockIdx.x;
    __shared__ float s[NCLS];
    __shared__ float rv[256];
    __shared__ int   ri[256];
    __shared__ float selv[TOPK];
    __shared__ int   seli[TOPK];

    int tid = threadIdx.x;
    float invT = 1.0f / temp[0];
    for (int i = tid; i < NCLS; i += 256) s[i] = scores[(long)t * NCLS + i] * invT;
    __syncthreads();

    // max
    float m = -INFINITY;
    for (int i = tid; i < NCLS; i += 256) m = fmaxf(m, s[i]);
    rv[tid] = m; __syncthreads();
    for (int o = 128; o > 0; o >>= 1) { if (tid < o) rv[tid] = fmaxf(rv[tid], rv[tid + o]); __syncthreads(); }
    m = rv[0]; __syncthreads();

    // denom
    float sum = 0.0f;
    for (int i = tid; i < NCLS; i += 256) sum += expf(s[i] - m);
    rv[tid] = sum; __syncthreads();
    for (int o = 128; o > 0; o >>= 1) { if (tid < o) rv[tid] += rv[tid + o]; __syncthreads(); }
    float denom = rv[0]; __syncthreads();

    // top-8 (ties -> lower index, matching lax.top_k)
    for (int it = 0; it < TOPK; it++) {
        float bv = -INFINITY; int bi = -1;
        for (int i = tid; i < NCLS; i += 256) {
            bool used = false;
            for (int j = 0; j < it; j++) if (seli[j] == i) used = true;
            if (!used) {
                float v = s[i];
                if (v > bv || (v == bv && (unsigned)i < (unsigned)bi)) { bv = v; bi = i; }
            }
        }
        rv[tid] = bv; ri[tid] = bi; __syncthreads();
        for (int o = 128; o > 0; o >>= 1) {
            if (tid < o) {
                if (rv[tid + o] > rv[tid] ||
                    (rv[tid + o] == rv[tid] && (unsigned)ri[tid + o] < (unsigned)ri[tid])) {
                    rv[tid] = rv[tid + o]; ri[tid] = ri[tid + o];
                }
            }
            __syncthreads();
        }
        if (tid == 0) { selv[it] = rv[0]; seli[it] = ri[0]; }
        __syncthreads();
    }

    if (tid < TOPK) {
        int idx = seli[tid];
        float p = expf(selv[tid] - m) / denom;
        float w = (p >= 1e-6f) ? p : 0.0f;
        int pe = idx >> 8;
        int rem = idx & 255;
        int me = rem >> 4;
        int qe = rem & 15;
        int r = t * TOPK + tid;
        preE[r] = pe; mlpE[r] = me; postE[r] = qe; wgt[r] = w;
        atomicAdd(&cnt[pe], 1);
        atomicAdd(&cnt[16 + me], 1);
        atomicAdd(&cnt[32 + qe], 1);
    }
}

__global__ void zero_k(int* cnt, int* cur) {
    int i = threadIdx.x;
    if (i < 48) { cnt[i] = 0; cur[i] = 0; }
}

__global__ void scan_k(const int* __restrict__ cnt, int* __restrict__ off) {
    if (threadIdx.x == 0) {
        for (int gp = 0; gp < 3; gp++) {
            int a = 0;
            for (int i = 0; i < 16; i++) { off[gp * 17 + i] = a; a += cnt[gp * 16 + i]; }
            off[gp * 17 + 16] = a;
        }
    }
}

__global__ void scatter_k(const int* __restrict__ preE, const int* __restrict__ mlpE,
                          const int* __restrict__ postE, const int* __restrict__ off,
                          int* __restrict__ cur,
                          int* __restrict__ permP, int* __restrict__ permM, int* __restrict__ permQ)
{
    int i = blockIdx.x * blockDim.x + threadIdx.x;
    if (i >= NROWS) return;
    int e, p;
    e = preE[i];  p = off[e]       + atomicAdd(&cur[e],      1); permP[p] = i;
    e = mlpE[i];  p = off[17 + e]  + atomicAdd(&cur[16 + e], 1); permM[p] = i;
    e = postE[i]; p = off[34 + e]  + atomicAdd(&cur[32 + e], 1); permQ[p] = i;
}

// ---------------- row layernorm (+optional act) ----------------
// MODE 0: pre (always LN, then act by e&3).  MODE 1: post (LN only if e even, no act)
template<int MODE>
__global__ __launch_bounds__(256)
void ln_k(const float* __restrict__ in, float* __restrict__ out,
          const int* __restrict__ eArr, const float* __restrict__ g, const float* __restrict__ be)
{
    int row = blockIdx.x;
    int e = eArr[row];
    const float* xp = in + (long)row * D512;
    float* yp = out + (long)row * D512;
    int tid = threadIdx.x;
    float v0 = xp[tid], v1 = xp[tid + 256];
    if (MODE == 1 && (e & 1)) { yp[tid] = v0; yp[tid + 256] = v1; return; }

    __shared__ float red[256];
    red[tid] = v0 + v1; __syncthreads();
    for (int o = 128; o > 0; o >>= 1) { if (tid < o) red[tid] += red[tid + o]; __syncthreads(); }
    float mu = red[0] * (1.0f / 512.0f);
    __syncthreads();
    float d0 = v0 - mu, d1 = v1 - mu;
    red[tid] = d0 * d0 + d1 * d1; __syncthreads();
    for (int o = 128; o > 0; o >>= 1) { if (tid < o) red[tid] += red[tid + o]; __syncthreads(); }
    float rstd = rsqrtf(red[0] * (1.0f / 512.0f) + 1e-5f);

    float y0 = d0 * rstd * g[e * D512 + tid]       + be[e * D512 + tid];
    float y1 = d1 * rstd * g[e * D512 + tid + 256] + be[e * D512 + tid + 256];
    if (MODE == 0) { y0 = act_apply(e, y0); y1 = act_apply(e, y1); }
    yp[tid] = y0; yp[tid + 256] = y1;
}

// ---------------- weighted combine ----------------
__global__ void final_k(const float* __restrict__ z, const float* __restrict__ wgt,
                        float* __restrict__ out)
{
    int t = blockIdx.x, d = threadIdx.x;
    float acc = 0.0f;
#pragma unroll
    for (int k = 0; k < TOPK; k++) {
        int r = t * TOPK + k;
        acc += wgt[r] * z[(long)r * D512 + d];
    }
    out[(long)t * D512 + d] = acc;
}

// ---------------- launch ----------------
template <typename Tv>
static float* symf(Tv& v) { void* p = nullptr; cudaGetSymbolAddress(&p, v); return (float*)p; }
template <typename Tv>
static int* symi(Tv& v) { void* p = nullptr; cudaGetSymbolAddress(&p, v); return (int*)p; }

extern "C" void kernel_launch(void* const* d_in, const int* in_sizes, int n_in,
                              void* d_out, int out_size)
{
    const float* x      = (const float*)d_in[0];
    const float* r_w1   = (const float*)d_in[1];
    const float* r_b1   = (const float*)d_in[2];
    const float* r_w2   = (const float*)d_in[3];
    const float* r_b2   = (const float*)d_in[4];
    const float* r_w3   = (const float*)d_in[5];
    const float* r_b3   = (const float*)d_in[6];
    const float* temp   = (const float*)d_in[7];
    const float* pre_w  = (const float*)d_in[8];
    const float* pre_b  = (const float*)d_in[9];
    const float* pre_g  = (const float*)d_in[10];
    const float* pre_be = (const float*)d_in[11];
    const float* mlp_w1 = (const float*)d_in[12];
    const float* mlp_b1 = (const float*)d_in[13];
    const float* mlp_w2 = (const float*)d_in[14];
    const float* mlp_b2 = (const float*)d_in[15];
    const float* post_w = (const float*)d_in[16];
    const float* post_b = (const float*)d_in[17];
    const float* post_g = (const float*)d_in[18];
    const float* post_be= (const float*)d_in[19];
    float* out = (float*)d_out;

    float* h1     = symf(g_h1);
    float* h2     = symf(g_h2);
    float* scores = symf(g_scores);
    float* lin    = symf(g_lin);
    float* xin    = symf(g_xin);
    float* hid    = symf(g_hid);
    float* mout   = symf(g_mlpout);
    float* zbuf   = symf(g_z);
    float* wgt    = symf(g_wgt);
    int* preE  = symi(g_preE);
    int* mlpE  = symi(g_mlpE);
    int* postE = symi(g_postE);
    int* cnt   = symi(g_cnt);
    int* cur   = symi(g_cur);
    int* off   = symi(g_off);
    int* permP = symi(g_permP);
    int* permM = symi(g_permM);
    int* permQ = symi(g_permQ);

    // router
    gemm_k<1, 0><<<dim3(4, 8, 1), 256>>>(x, 512, 0, r_w1, 0, 512, r_b1, 0, h1, 512, 256, 512, nullptr, nullptr);
    gemm_k<1, 0><<<dim3(2, 8, 1), 256>>>(h1, 512, 0, r_w2, 0, 256, r_b2, 0, h2, 256, 256, 512, nullptr, nullptr);
    gemm_k<0, 0><<<dim3(32, 8, 1), 256>>>(h2, 256, 0, r_w3, 0, 4096, r_b3, 0, scores, 4096, 256, 256, nullptr, nullptr);

    // routing
    zero_k<<<1, 64>>>(cnt, cur);
    topk_k<<<256, 256>>>(scores, temp, preE, mlpE, postE, wgt, cnt);
    scan_k<<<1, 32>>>(cnt, off);
    scatter_k<<<8, 256>>>(preE, mlpE, postE, off, cur, permP, permM, permQ);

    // pre experts: linear -> LN + act
    gemm_k<0, 0><<<dim3(4, 64, 16), 256>>>(x, 512, 3, pre_w, 512L * 512, 512, pre_b, 512,
                                           lin, 512, 0, 512, permP, off);
    ln_k<0><<<2048, 256>>>(lin, xin, preE, pre_g, pre_be);

    // mlp experts
    gemm_k<2, 1><<<dim3(20, 64, 16), 256>>>(xin, 512, 0, mlp_w1, 512L * 2560, 2560, mlp_b1, 2560,
                                            hid, 2560, 0, 512, permM, off + 17);
    gemm_k<0, 2><<<dim3(4, 64, 16), 256>>>(hid, 2560, 0, mlp_w2, 2560L * 512, 512, mlp_b2, 512,
                                           mout, 512, 0, 0, permM, off + 17);

    // post experts: linear -> optional LN
    gemm_k<0, 0><<<dim3(4, 64, 16), 256>>>(mout, 512, 0, post_w, 512L * 512, 512, post_b, 512,
                                           lin, 512, 0, 512, permQ, off + 34);
    ln_k<1><<<2048, 256>>>(lin, zbuf, postE, post_g, post_be);

    // weighted combine
    final_k<<<256, 512>>>(zbuf, wgt, out);
    (void)in_sizes; (void)n_in; (void)out_size;
}

// round 4
// speedup vs baseline: 1.0459x; 1.0459x over previous
#include <cuda_runtime.h>
#include <cuda_bf16.h>
#include <math.h>
#include <stdint.h>

// Problem constants
#define D512 512
#define T256 256
#define NROWS 2048          // T * TOPK
#define MAXH 2560
#define NEXP 16
#define NCLS 4096
#define TOPK 8

// ---------------- scratch (device globals; no allocation allowed) ----------
__device__ float g_h1[T256 * D512];
__device__ float g_h2[T256 * 256];
__device__ float g_scores[T256 * NCLS];
__device__ float g_lin[NROWS * D512];      // pre linear, later reused for post linear
__device__ float g_xin[NROWS * D512];      // pre output after LN+act
__device__ float g_hid[NROWS * MAXH];      // mlp hidden
__device__ float g_mlpout[NROWS * D512];
__device__ float g_z[NROWS * D512];        // post output (after optional LN)
__device__ int   g_preE[NROWS];
__device__ int   g_mlpE[NROWS];
__device__ int   g_postE[NROWS];
__device__ float g_wgt[NROWS];
__device__ int   g_cnt[48];
__device__ int   g_cur[48];
__device__ int   g_off[51];                // 3 x 17
__device__ int   g_permP[NROWS];
__device__ int   g_permM[NROWS];
__device__ int   g_permQ[NROWS];

// ---------------- activations ----------------
__device__ __forceinline__ float act_apply(int a, float v) {
    switch (a & 3) {
        case 0:  return 0.5f * v * (1.0f + erff(v * 0.70710678118654752f)); // exact gelu
        case 1:  return fmaxf(v, 0.0f);                                      // relu
        case 2:  return tanhf(v);                                            // tanh
        default: return v * (1.0f / (1.0f + expf(-v)));                      // silu
    }
}

__device__ __forceinline__ float to_tf32(float x) {
    uint32_t u;
    asm("cvt.rna.tf32.f32 %0, %1;" : "=r"(u) : "f"(x));
    return __uint_as_float(u);
}

__device__ __forceinline__ void mma_tf32(float c[4], const uint32_t a[4], const uint32_t b[2]) {
    asm volatile(
        "mma.sync.aligned.m16n8k8.row.col.f32.tf32.tf32.f32 "
        "{%0,%1,%2,%3}, {%4,%5,%6,%7}, {%8,%9}, {%0,%1,%2,%3};"
        : "+f"(c[0]), "+f"(c[1]), "+f"(c[2]), "+f"(c[3])
        : "r"(a[0]), "r"(a[1]), "r"(a[2]), "r"(a[3]), "r"(b[0]), "r"(b[1]));
}

// ================= fp32 FFMA GEMM (router only: precision-critical) ========
#define BM 32
#define BN 128
#define BK 16

template<int ACT>
__global__ __launch_bounds__(256)
void gemm_k(const float* __restrict__ X, int ldx,
            const float* __restrict__ W, int ldw,
            const float* __restrict__ bias,
            float* __restrict__ Y, int ldy,
            int M, int K)
{
    int n0 = blockIdx.x * BN;
    int m0 = blockIdx.y * BM;
    if (m0 >= M) return;

    __shared__ float Xs[BK][BM];
    __shared__ float Ws[BK][BN];

    int tid = threadIdx.x;
    int tx = tid & 31, ty = tid >> 5;
    int c0 = tx * 4, r0 = ty * 4;

    float acc[4][4];
#pragma unroll
    for (int i = 0; i < 4; i++)
#pragma unroll
        for (int j = 0; j < 4; j++) acc[i][j] = 0.0f;

    int xm = tid >> 2, xk = (tid & 3) * 4;
    const float* xp = X + (long)(m0 + xm) * ldx;
    bool xok = (tid < 128) && (m0 + xm < M);

    for (int k0 = 0; k0 < K; k0 += BK) {
        const float* wp = W + (long)(k0 + ty) * ldw + n0 + c0;
        float4 w0 = *(const float4*)wp;
        float4 w1 = *(const float4*)(wp + (long)8 * ldw);
        float4 xv = make_float4(0.f, 0.f, 0.f, 0.f);
        if (xok) xv = *(const float4*)(xp + k0 + xk);

        *(float4*)&Ws[ty][c0]     = w0;
        *(float4*)&Ws[ty + 8][c0] = w1;
        if (tid < 128) {
            Xs[xk + 0][xm] = xv.x; Xs[xk + 1][xm] = xv.y;
            Xs[xk + 2][xm] = xv.z; Xs[xk + 3][xm] = xv.w;
        }
        __syncthreads();

#pragma unroll
        for (int kk = 0; kk < BK; kk++) {
            float4 a = *(const float4*)&Xs[kk][r0];
            float4 b = *(const float4*)&Ws[kk][c0];
            acc[0][0] += a.x * b.x; acc[0][1] += a.x * b.y; acc[0][2] += a.x * b.z; acc[0][3] += a.x * b.w;
            acc[1][0] += a.y * b.x; acc[1][1] += a.y * b.y; acc[1][2] += a.y * b.z; acc[1][3] += a.y * b.w;
            acc[2][0] += a.z * b.x; acc[2][1] += a.z * b.y; acc[2][2] += a.z * b.z; acc[2][3] += a.z * b.w;
            acc[3][0] += a.w * b.x; acc[3][1] += a.w * b.y; acc[3][2] += a.w * b.z; acc[3][3] += a.w * b.w;
        }
        __syncthreads();
    }

    float4 bb = *(const float4*)(bias + n0 + c0);
#pragma unroll
    for (int i = 0; i < 4; i++) {
        int r = m0 + r0 + i;
        if (r >= M) continue;
        float4 o;
        o.x = acc[i][0] + bb.x; o.y = acc[i][1] + bb.y;
        o.z = acc[i][2] + bb.z; o.w = acc[i][3] + bb.w;
        if (ACT == 1) {
            o.x = act_apply(0, o.x); o.y = act_apply(0, o.y);
            o.z = act_apply(0, o.z); o.w = act_apply(0, o.w);
        }
        *(float4*)(Y + (long)r * ldy + n0 + c0) = o;
    }
}

// ================= tf32 tensor-core grouped GEMM (expert GEMMs) ============
// BM=64, BN=128, BK=16; 8 warps, each 32x32 via m16n8k8 tf32 mma.sync.
// ACT: 0 none, 2 act by (e&3). NKMODE: 0 none, 1 skip n0>=he, 2 Keff=he.
template<int ACT, int NKMODE>
__global__ __launch_bounds__(256)
void gemm_tc(const float* __restrict__ X, int ldx, int xshift,
             const float* __restrict__ W, long wstride, int ldw,
             const float* __restrict__ bias, int bstride,
             float* __restrict__ Y, int ldy,
             int K,
             const int* __restrict__ perm, const int* __restrict__ segoff)
{
    int e  = blockIdx.z;
    int n0 = blockIdx.x * 128;
    int he = 512 * (2 + (e >> 2));
    if (NKMODE == 1 && n0 >= he) return;
    int Keff = (NKMODE == 2) ? he : K;

    int segs = segoff[e], sege = segoff[e + 1];
    int m0 = segs + blockIdx.y * 64;
    if (m0 >= sege) return;

    __shared__ float Xs[2][64][28];    // stride 28: conflict-free A-frag reads
    __shared__ float Ws[2][16][132];   // stride 132: conflict-free B-frag reads
    __shared__ int   rows[64];

    int tid = threadIdx.x;
    if (tid < 64) {
        int p = m0 + tid;
        rows[tid] = (p < sege) ? perm[p] : -1;
    }
    __syncthreads();

    const float* Wb = W + (long)e * wstride;

    // loader mapping
    int wrow = tid >> 5, wc4 = (tid & 31) * 4;   // W: rows wrow, wrow+8; 128 cols
    int xrow = tid >> 2, xc4 = (tid & 3) * 4;    // X: 64 rows x 16 cols
    int xr = rows[xrow];
    const float* xp = X + (long)((xr >= 0 ? xr : 0) >> xshift) * ldx;

    // preload tile 0
    {
        float4 w0 = *(const float4*)(Wb + (long)wrow * ldw + n0 + wc4);
        float4 w1 = *(const float4*)(Wb + (long)(wrow + 8) * ldw + n0 + wc4);
        float4 xv = make_float4(0.f, 0.f, 0.f, 0.f);
        if (xr >= 0) xv = *(const float4*)(xp + xc4);
        float4 tw0 = make_float4(to_tf32(w0.x), to_tf32(w0.y), to_tf32(w0.z), to_tf32(w0.w));
        float4 tw1 = make_float4(to_tf32(w1.x), to_tf32(w1.y), to_tf32(w1.z), to_tf32(w1.w));
        float4 txv = make_float4(to_tf32(xv.x), to_tf32(xv.y), to_tf32(xv.z), to_tf32(xv.w));
        *(float4*)&Ws[0][wrow][wc4]     = tw0;
        *(float4*)&Ws[0][wrow + 8][wc4] = tw1;
        *(float4*)&Xs[0][xrow][xc4]     = txv;
    }
    __syncthreads();

    int lane = tid & 31, warp = tid >> 5;
    int wm = warp >> 2, wn = warp & 3;          // warp tile: (wm*32, wn*32)
    int lr = lane >> 2, lc = lane & 3;

    float c[2][4][4];
#pragma unroll
    for (int i = 0; i < 2; i++)
#pragma unroll
        for (int j = 0; j < 4; j++)
#pragma unroll
            for (int q = 0; q < 4; q++) c[i][j][q] = 0.0f;

    int nk = Keff >> 4;
    for (int t = 0; t < nk; t++) {
        int buf = t & 1;
        bool more = (t + 1 < nk);
        float4 w0, w1, xv;
        if (more) {
            int k0 = (t + 1) << 4;
            w0 = *(const float4*)(Wb + (long)(k0 + wrow) * ldw + n0 + wc4);
            w1 = *(const float4*)(Wb + (long)(k0 + wrow + 8) * ldw + n0 + wc4);
            xv = make_float4(0.f, 0.f, 0.f, 0.f);
            if (xr >= 0) xv = *(const float4*)(xp + k0 + xc4);
        }

#pragma unroll
        for (int ks = 0; ks < 16; ks += 8) {
            uint32_t a[2][4], b[4][2];
#pragma unroll
            for (int i = 0; i < 2; i++) {
                int bm = wm * 32 + i * 16;
                a[i][0] = __float_as_uint(Xs[buf][bm + lr    ][ks + lc    ]);
                a[i][1] = __float_as_uint(Xs[buf][bm + lr + 8][ks + lc    ]);
                a[i][2] = __float_as_uint(Xs[buf][bm + lr    ][ks + lc + 4]);
                a[i][3] = __float_as_uint(Xs[buf][bm + lr + 8][ks + lc + 4]);
            }
#pragma unroll
            for (int j = 0; j < 4; j++) {
                int bn = wn * 32 + j * 8 + lr;
                b[j][0] = __float_as_uint(Ws[buf][ks + lc    ][bn]);
                b[j][1] = __float_as_uint(Ws[buf][ks + lc + 4][bn]);
            }
#pragma unroll
            for (int i = 0; i < 2; i++)
#pragma unroll
                for (int j = 0; j < 4; j++)
                    mma_tf32(c[i][j], a[i], b[j]);
        }

        if (more) {
            int nb = buf ^ 1;
            float4 tw0 = make_float4(to_tf32(w0.x), to_tf32(w0.y), to_tf32(w0.z), to_tf32(w0.w));
            float4 tw1 = make_float4(to_tf32(w1.x), to_tf32(w1.y), to_tf32(w1.z), to_tf32(w1.w));
            float4 txv = make_float4(to_tf32(xv.x), to_tf32(xv.y), to_tf32(xv.z), to_tf32(xv.w));
            *(float4*)&Ws[nb][wrow][wc4]     = tw0;
            *(float4*)&Ws[nb][wrow + 8][wc4] = tw1;
            *(float4*)&Xs[nb][xrow][xc4]     = txv;
        }
        __syncthreads();
    }

    // epilogue: bias + optional act, scatter by original row ids
#pragma unroll
    for (int j = 0; j < 4; j++) {
        int n = n0 + wn * 32 + j * 8 + 2 * lc;
        float2 bb = *(const float2*)(bias + (long)e * bstride + n);
#pragma unroll
        for (int i = 0; i < 2; i++) {
            int base = wm * 32 + i * 16 + lr;
            int ra = rows[base];
            int rb = rows[base + 8];
            if (ra >= 0) {
                float o0 = c[i][j][0] + bb.x, o1 = c[i][j][1] + bb.y;
                if (ACT == 2) { o0 = act_apply(e, o0); o1 = act_apply(e, o1); }
                float2 o = make_float2(o0, o1);
                *(float2*)(Y + (long)ra * ldy + n) = o;
            }
            if (rb >= 0) {
                float o0 = c[i][j][2] + bb.x, o1 = c[i][j][3] + bb.y;
                if (ACT == 2) { o0 = act_apply(e, o0); o1 = act_apply(e, o1); }
                float2 o = make_float2(o0, o1);
                *(float2*)(Y + (long)rb * ldy + n) = o;
            }
        }
    }
}

// ---------------- softmax + top-8 + route decompose ----------------
__global__ __launch_bounds__(256)
void topk_k(const float* __restrict__ scores, const float* __restrict__ temp,
            int* __restrict__ preE, int* __restrict__ mlpE, int* __restrict__ postE,
            float* __restrict__ wgt, int* __restrict__ cnt)
{
    int t = blockIdx.x;
    __shared__ float s[NCLS];
    __shared__ float rv[256];
    __shared__ int   ri[256];
    __shared__ float selv[TOPK];
    __shared__ int   seli[TOPK];

    int tid = threadIdx.x;
    float invT = 1.0f / temp[0];
    for (int i = tid; i < NCLS; i += 256) s[i] = scores[(long)t * NCLS + i] * invT;
    __syncthreads();

    float m = -INFINITY;
    for (int i = tid; i < NCLS; i += 256) m = fmaxf(m, s[i]);
    rv[tid] = m; __syncthreads();
    for (int o = 128; o > 0; o >>= 1) { if (tid < o) rv[tid] = fmaxf(rv[tid], rv[tid + o]); __syncthreads(); }
    m = rv[0]; __syncthreads();

    float sum = 0.0f;
    for (int i = tid; i < NCLS; i += 256) sum += expf(s[i] - m);
    rv[tid] = sum; __syncthreads();
    for (int o = 128; o > 0; o >>= 1) { if (tid < o) rv[tid] += rv[tid + o]; __syncthreads(); }
    float denom = rv[0]; __syncthreads();

    for (int it = 0; it < TOPK; it++) {
        float bv = -INFINITY; int bi = -1;
        for (int i = tid; i < NCLS; i += 256) {
            bool used = false;
            for (int j = 0; j < it; j++) if (seli[j] == i) used = true;
            if (!used) {
                float v = s[i];
                if (v > bv || (v == bv && (unsigned)i < (unsigned)bi)) { bv = v; bi = i; }
            }
        }
        rv[tid] = bv; ri[tid] = bi; __syncthreads();
        for (int o = 128; o > 0; o >>= 1) {
            if (tid < o) {
                if (rv[tid + o] > rv[tid] ||
                    (rv[tid + o] == rv[tid] && (unsigned)ri[tid + o] < (unsigned)ri[tid])) {
                    rv[tid] = rv[tid + o]; ri[tid] = ri[tid + o];
                }
            }
            __syncthreads();
        }
        if (tid == 0) { selv[it] = rv[0]; seli[it] = ri[0]; }
        __syncthreads();
    }

    if (tid < TOPK) {
        int idx = seli[tid];
        float p = expf(selv[tid] - m) / denom;
        float w = (p >= 1e-6f) ? p : 0.0f;
        int pe = idx >> 8;
        int rem = idx & 255;
        int me = rem >> 4;
        int qe = rem & 15;
        int r = t * TOPK + tid;
        preE[r] = pe; mlpE[r] = me; postE[r] = qe; wgt[r] = w;
        atomicAdd(&cnt[pe], 1);
        atomicAdd(&cnt[16 + me], 1);
        atomicAdd(&cnt[32 + qe], 1);
    }
}

__global__ void zero_k(int* cnt, int* cur) {
    int i = threadIdx.x;
    if (i < 48) { cnt[i] = 0; cur[i] = 0; }
}

__global__ void scan_k(const int* __restrict__ cnt, int* __restrict__ off) {
    if (threadIdx.x == 0) {
        for (int gp = 0; gp < 3; gp++) {
            int a = 0;
            for (int i = 0; i < 16; i++) { off[gp * 17 + i] = a; a += cnt[gp * 16 + i]; }
            off[gp * 17 + 16] = a;
        }
    }
}

__global__ void scatter_k(const int* __restrict__ preE, const int* __restrict__ mlpE,
                          const int* __restrict__ postE, const int* __restrict__ off,
                          int* __restrict__ cur,
                          int* __restrict__ permP, int* __restrict__ permM, int* __restrict__ permQ)
{
    int i = blockIdx.x * blockDim.x + threadIdx.x;
    if (i >= NROWS) return;
    int e, p;
    e = preE[i];  p = off[e]       + atomicAdd(&cur[e],      1); permP[p] = i;
    e = mlpE[i];  p = off[17 + e]  + atomicAdd(&cur[16 + e], 1); permM[p] = i;
    e = postE[i]; p = off[34 + e]  + atomicAdd(&cur[32 + e], 1); permQ[p] = i;
}

// ---------------- row layernorm (+optional act) ----------------
template<int MODE>
__global__ __launch_bounds__(256)
void ln_k(const float* __restrict__ in, float* __restrict__ out,
          const int* __restrict__ eArr, const float* __restrict__ g, const float* __restrict__ be)
{
    int row = blockIdx.x;
    int e = eArr[row];
    const float* xp = in + (long)row * D512;
    float* yp = out + (long)row * D512;
    int tid = threadIdx.x;
    float v0 = xp[tid], v1 = xp[tid + 256];
    if (MODE == 1 && (e & 1)) { yp[tid] = v0; yp[tid + 256] = v1; return; }

    __shared__ float red[256];
    red[tid] = v0 + v1; __syncthreads();
    for (int o = 128; o > 0; o >>= 1) { if (tid < o) red[tid] += red[tid + o]; __syncthreads(); }
    float mu = red[0] * (1.0f / 512.0f);
    __syncthreads();
    float d0 = v0 - mu, d1 = v1 - mu;
    red[tid] = d0 * d0 + d1 * d1; __syncthreads();
    for (int o = 128; o > 0; o >>= 1) { if (tid < o) red[tid] += red[tid + o]; __syncthreads(); }
    float rstd = rsqrtf(red[0] * (1.0f / 512.0f) + 1e-5f);

    float y0 = d0 * rstd * g[e * D512 + tid]       + be[e * D512 + tid];
    float y1 = d1 * rstd * g[e * D512 + tid + 256] + be[e * D512 + tid + 256];
    if (MODE == 0) { y0 = act_apply(e, y0); y1 = act_apply(e, y1); }
    yp[tid] = y0; yp[tid + 256] = y1;
}

// ---------------- weighted combine ----------------
__global__ void final_k(const float* __restrict__ z, const float* __restrict__ wgt,
                        float* __restrict__ out)
{
    int t = blockIdx.x, d = threadIdx.x;
    float acc = 0.0f;
#pragma unroll
    for (int k = 0; k < TOPK; k++) {
        int r = t * TOPK + k;
        acc += wgt[r] * z[(long)r * D512 + d];
    }
    out[(long)t * D512 + d] = acc;
}

// ---------------- launch ----------------
template <typename Tv>
static float* symf(Tv& v) { void* p = nullptr; cudaGetSymbolAddress(&p, v); return (float*)p; }
template <typename Tv>
static int* symi(Tv& v) { void* p = nullptr; cudaGetSymbolAddress(&p, v); return (int*)p; }

extern "C" void kernel_launch(void* const* d_in, const int* in_sizes, int n_in,
                              void* d_out, int out_size)
{
    const float* x      = (const float*)d_in[0];
    const float* r_w1   = (const float*)d_in[1];
    const float* r_b1   = (const float*)d_in[2];
    const float* r_w2   = (const float*)d_in[3];
    const float* r_b2   = (const float*)d_in[4];
    const float* r_w3   = (const float*)d_in[5];
    const float* r_b3   = (const float*)d_in[6];
    const float* temp   = (const float*)d_in[7];
    const float* pre_w  = (const float*)d_in[8];
    const float* pre_b  = (const float*)d_in[9];
    const float* pre_g  = (const float*)d_in[10];
    const float* pre_be = (const float*)d_in[11];
    const float* mlp_w1 = (const float*)d_in[12];
    const float* mlp_b1 = (const float*)d_in[13];
    const float* mlp_w2 = (const float*)d_in[14];
    const float* mlp_b2 = (const float*)d_in[15];
    const float* post_w = (const float*)d_in[16];
    const float* post_b = (const float*)d_in[17];
    const float* post_g = (const float*)d_in[18];
    const float* post_be= (const float*)d_in[19];
    float* out = (float*)d_out;

    float* h1     = symf(g_h1);
    float* h2     = symf(g_h2);
    float* scores = symf(g_scores);
    float* lin    = symf(g_lin);
    float* xin    = symf(g_xin);
    float* hid    = symf(g_hid);
    float* mout   = symf(g_mlpout);
    float* zbuf   = symf(g_z);
    float* wgt    = symf(g_wgt);
    int* preE  = symi(g_preE);
    int* mlpE  = symi(g_mlpE);
    int* postE = symi(g_postE);
    int* cnt   = symi(g_cnt);
    int* cur   = symi(g_cur);
    int* off   = symi(g_off);
    int* permP = symi(g_permP);
    int* permM = symi(g_permM);
    int* permQ = symi(g_permQ);

    // router (fp32 — top-k selection is precision-critical)
    gemm_k<1><<<dim3(4, 8, 1), 256>>>(x, 512, r_w1, 512, r_b1, h1, 512, 256, 512);
    gemm_k<1><<<dim3(2, 8, 1), 256>>>(h1, 512, r_w2, 256, r_b2, h2, 256, 256, 512);
    gemm_k<0><<<dim3(32, 8, 1), 256>>>(h2, 256, r_w3, 4096, r_b3, scores, 4096, 256, 256);

    // routing
    zero_k<<<1, 64>>>(cnt, cur);
    topk_k<<<256, 256>>>(scores, temp, preE, mlpE, postE, wgt, cnt);
    scan_k<<<1, 32>>>(cnt, off);
    scatter_k<<<8, 256>>>(preE, mlpE, postE, off, cur, permP, permM, permQ);

    // pre experts: linear -> LN + act   (tf32 tensor cores)
    gemm_tc<0, 0><<<dim3(4, 32, 16), 256>>>(x, 512, 3, pre_w, 512L * 512, 512, pre_b, 512,
                                            lin, 512, 512, permP, off);
    ln_k<0><<<2048, 256>>>(lin, xin, preE, pre_g, pre_be);

    // mlp experts
    gemm_tc<2, 1><<<dim3(20, 32, 16), 256>>>(xin, 512, 0, mlp_w1, 512L * 2560, 2560, mlp_b1, 2560,
                                             hid, 2560, 512, permM, off + 17);
    gemm_tc<0, 2><<<dim3(4, 32, 16), 256>>>(hid, 2560, 0, mlp_w2, 2560L * 512, 512, mlp_b2, 512,
                                            mout, 512, 0, permM, off + 17);

    // post experts: linear -> optional LN
    gemm_tc<0, 0><<<dim3(4, 32, 16), 256>>>(mout, 512, 0, post_w, 512L * 512, 512, post_b, 512,
                                            lin, 512, 512, permQ, off + 34);
    ln_k<1><<<2048, 256>>>(lin, zbuf, postE, post_g, post_be);

    // weighted combine
    final_k<<<256, 512>>>(zbuf, wgt, out);
    (void)in_sizes; (void)n_in; (void)out_size;
}

// round 9
// speedup vs baseline: 1.5751x; 1.5059x over previous
#include <cuda_runtime.h>
#include <cuda_bf16.h>
#include <math.h>
#include <stdint.h>

// Problem constants
#define D512 512
#define T256 256
#define NROWS 2048          // T * TOPK
#define MAXH 2560
#define NEXP 16
#define NCLS 4096
#define TOPK 8

// ---------------- scratch (device globals; no allocation allowed) ----------
__device__ float g_h1[T256 * D512];
__device__ float g_h2[T256 * 256];
__device__ float g_scores[T256 * NCLS];
__device__ float g_lin[NROWS * D512];
__device__ float g_xin[NROWS * D512];
__device__ float g_hid[NROWS * MAXH];
__device__ float g_mlpout[NROWS * D512];
__device__ float g_z[NROWS * D512];
__device__ int   g_preE[NROWS];
__device__ int   g_mlpE[NROWS];
__device__ int   g_postE[NROWS];
__device__ float g_wgt[NROWS];
__device__ int   g_cnt[48];
__device__ int   g_cur[48];
__device__ int   g_off[51];
__device__ int   g_permP[NROWS];
__device__ int   g_permM[NROWS];
__device__ int   g_permQ[NROWS];

// ---------------- activations ----------------
__device__ __forceinline__ float act_apply(int a, float v) {
    switch (a & 3) {
        case 0:  return 0.5f * v * (1.0f + erff(v * 0.70710678118654752f));
        case 1:  return fmaxf(v, 0.0f);
        case 2:  return tanhf(v);
        default: return v * (1.0f / (1.0f + expf(-v)));
    }
}

__device__ __forceinline__ uint32_t to_tf32_u(float x) {
    uint32_t u;
    asm("cvt.rna.tf32.f32 %0, %1;" : "=r"(u) : "f"(x));
    return u;
}

__device__ __forceinline__ void mma_tf32(float c[4], const uint32_t a[4], const uint32_t b[2]) {
    asm volatile(
        "mma.sync.aligned.m16n8k8.row.col.f32.tf32.tf32.f32 "
        "{%0,%1,%2,%3}, {%4,%5,%6,%7}, {%8,%9}, {%0,%1,%2,%3};"
        : "+f"(c[0]), "+f"(c[1]), "+f"(c[2]), "+f"(c[3])
        : "r"(a[0]), "r"(a[1]), "r"(a[2]), "r"(a[3]), "r"(b[0]), "r"(b[1]));
}

__device__ __forceinline__ void cp16(uint32_t smem_addr, const void* gptr, bool valid) {
    int sz = valid ? 16 : 0;
    asm volatile("cp.async.ca.shared.global [%0], [%1], 16, %2;"
                 :: "r"(smem_addr), "l"(gptr), "r"(sz));
}
__device__ __forceinline__ void cp_commit() {
    asm volatile("cp.async.commit_group;");
}
template<int N>
__device__ __forceinline__ void cp_wait() {
    asm volatile("cp.async.wait_group %0;" :: "n"(N));
}

// ================= fp32 FFMA GEMM (router only: precision-critical) ========
#define BM 32
#define BN 128
#define BK 16

template<int ACT>
__global__ __launch_bounds__(256)
void gemm_k(const float* __restrict__ X, int ldx,
            const float* __restrict__ W, int ldw,
            const float* __restrict__ bias,
            float* __restrict__ Y, int ldy,
            int M, int K)
{
    int n0 = blockIdx.x * BN;
    int m0 = blockIdx.y * BM;
    if (m0 >= M) return;

    __shared__ float Xs[BK][BM];
    __shared__ float Ws[BK][BN];

    int tid = threadIdx.x;
    int tx = tid & 31, ty = tid >> 5;
    int c0 = tx * 4, r0 = ty * 4;

    float acc[4][4];
#pragma unroll
    for (int i = 0; i < 4; i++)
#pragma unroll
        for (int j = 0; j < 4; j++) acc[i][j] = 0.0f;

    int xm = tid >> 2, xk = (tid & 3) * 4;
    const float* xp = X + (long)(m0 + xm) * ldx;
    bool xok = (tid < 128) && (m0 + xm < M);

    for (int k0 = 0; k0 < K; k0 += BK) {
        const float* wp = W + (long)(k0 + ty) * ldw + n0 + c0;
        float4 w0 = *(const float4*)wp;
        float4 w1 = *(const float4*)(wp + (long)8 * ldw);
        float4 xv = make_float4(0.f, 0.f, 0.f, 0.f);
        if (xok) xv = *(const float4*)(xp + k0 + xk);

        *(float4*)&Ws[ty][c0]     = w0;
        *(float4*)&Ws[ty + 8][c0] = w1;
        if (tid < 128) {
            Xs[xk + 0][xm] = xv.x; Xs[xk + 1][xm] = xv.y;
            Xs[xk + 2][xm] = xv.z; Xs[xk + 3][xm] = xv.w;
        }
        __syncthreads();

#pragma unroll
        for (int kk = 0; kk < BK; kk++) {
            float4 a = *(const float4*)&Xs[kk][r0];
            float4 b = *(const float4*)&Ws[kk][c0];
            acc[0][0] += a.x * b.x; acc[0][1] += a.x * b.y; acc[0][2] += a.x * b.z; acc[0][3] += a.x * b.w;
            acc[1][0] += a.y * b.x; acc[1][1] += a.y * b.y; acc[1][2] += a.y * b.z; acc[1][3] += a.y * b.w;
            acc[2][0] += a.z * b.x; acc[2][1] += a.z * b.y; acc[2][2] += a.z * b.z; acc[2][3] += a.z * b.w;
            acc[3][0] += a.w * b.x; acc[3][1] += a.w * b.y; acc[3][2] += a.w * b.z; acc[3][3] += a.w * b.w;
        }
        __syncthreads();
    }

    float4 bb = *(const float4*)(bias + n0 + c0);
#pragma unroll
    for (int i = 0; i < 4; i++) {
        int r = m0 + r0 + i;
        if (r >= M) continue;
        float4 o;
        o.x = acc[i][0] + bb.x; o.y = acc[i][1] + bb.y;
        o.z = acc[i][2] + bb.z; o.w = acc[i][3] + bb.w;
        if (ACT == 1) {
            o.x = act_apply(0, o.x); o.y = act_apply(0, o.y);
            o.z = act_apply(0, o.z); o.w = act_apply(0, o.w);
        }
        *(float4*)(Y + (long)r * ldy + n0 + c0) = o;
    }
}

// ===== tf32 tensor-core grouped GEMM with 3-stage cp.async pipeline ========
// BM=64, BN=128, BK=16; 8 warps, each 32x32 via m16n8k8 tf32 mma.sync.
// smem holds raw fp32; cvt.rna.tf32 applied at fragment-load time.
#define STAGES 3
#define XPAD 28
#define WPAD 132

template<int ACT, int NKMODE>
__global__ __launch_bounds__(256)
void gemm_tc(const float* __restrict__ X, int ldx, int xshift,
             const float* __restrict__ W, long wstride, int ldw,
             const float* __restrict__ bias, int bstride,
             float* __restrict__ Y, int ldy,
             int K,
             const int* __restrict__ perm, const int* __restrict__ segoff)
{
    int e  = blockIdx.z;
    int n0 = blockIdx.x * 128;
    int he = 512 * (2 + (e >> 2));
    if (NKMODE == 1 && n0 >= he) return;
    int Keff = (NKMODE == 2) ? he : K;

    int segs = segoff[e], sege = segoff[e + 1];
    int m0 = segs + blockIdx.y * 64;
    if (m0 >= sege) return;

    __shared__ float Xs[STAGES][64][XPAD];
    __shared__ float Ws[STAGES][16][WPAD];
    __shared__ int   rows[64];

    int tid = threadIdx.x;
    if (tid < 64) {
        int p = m0 + tid;
        rows[tid] = (p < sege) ? perm[p] : -1;
    }
    __syncthreads();

    const float* Wb = W + (long)e * wstride;

    // loader mapping
    int wrow = tid >> 5, wc4 = (tid & 31) * 4;   // W: rows wrow, wrow+8
    int xrow = tid >> 2, xc4 = (tid & 3) * 4;    // X: 64 rows x 16 cols
    int xr = rows[xrow];
    const float* xp = X + (long)((xr >= 0 ? xr : 0) >> xshift) * ldx;
    bool xok = (xr >= 0);

    uint32_t xs_dst[STAGES], ws_dst0[STAGES], ws_dst1[STAGES];
#pragma unroll
    for (int s = 0; s < STAGES; s++) {
        xs_dst[s]  = (uint32_t)__cvta_generic_to_shared(&Xs[s][xrow][xc4]);
        ws_dst0[s] = (uint32_t)__cvta_generic_to_shared(&Ws[s][wrow][wc4]);
        ws_dst1[s] = (uint32_t)__cvta_generic_to_shared(&Ws[s][wrow + 8][wc4]);
    }

    int nk = Keff >> 4;

    // prologue: issue stages 0..STAGES-2
#pragma unroll
    for (int s = 0; s < STAGES - 1; s++) {
        if (s < nk) {
            int k0 = s << 4;
            cp16(ws_dst0[s], Wb + (long)(k0 + wrow) * ldw + n0 + wc4, true);
            cp16(ws_dst1[s], Wb + (long)(k0 + wrow + 8) * ldw + n0 + wc4, true);
            cp16(xs_dst[s],  xp + k0 + xc4, xok);
        }
        cp_commit();
    }

    int lane = tid & 31, warp = tid >> 5;
    int wm = warp >> 2, wn = warp & 3;
    int lr = lane >> 2, lc = lane & 3;

    float c[2][4][4];
#pragma unroll
    for (int i = 0; i < 2; i++)
#pragma unroll
        for (int j = 0; j < 4; j++)
#pragma unroll
            for (int q = 0; q < 4; q++) c[i][j][q] = 0.0f;

    for (int t = 0; t < nk; t++) {
        cp_wait<STAGES - 2>();
        __syncthreads();

        // issue tile t+STAGES-1 (overwrites buffer consumed in iter t-1)
        int tn = t + STAGES - 1;
        if (tn < nk) {
            int k0 = tn << 4;
            int s = tn % STAGES;
            cp16(ws_dst0[s], Wb + (long)(k0 + wrow) * ldw + n0 + wc4, true);
            cp16(ws_dst1[s], Wb + (long)(k0 + wrow + 8) * ldw + n0 + wc4, true);
            cp16(xs_dst[s],  xp + k0 + xc4, xok);
        }
        cp_commit();

        int buf = t % STAGES;
#pragma unroll
        for (int ks = 0; ks < 16; ks += 8) {
            uint32_t a[2][4], b[4][2];
#pragma unroll
            for (int i = 0; i < 2; i++) {
                int bm = wm * 32 + i * 16;
                a[i][0] = to_tf32_u(Xs[buf][bm + lr    ][ks + lc    ]);
                a[i][1] = to_tf32_u(Xs[buf][bm + lr + 8][ks + lc    ]);
                a[i][2] = to_tf32_u(Xs[buf][bm + lr    ][ks + lc + 4]);
                a[i][3] = to_tf32_u(Xs[buf][bm + lr + 8][ks + lc + 4]);
            }
#pragma unroll
            for (int j = 0; j < 4; j++) {
                int bn = wn * 32 + j * 8 + lr;
                b[j][0] = to_tf32_u(Ws[buf][ks + lc    ][bn]);
                b[j][1] = to_tf32_u(Ws[buf][ks + lc + 4][bn]);
            }
#pragma unroll
            for (int i = 0; i < 2; i++)
#pragma unroll
                for (int j = 0; j < 4; j++)
                    mma_tf32(c[i][j], a[i], b[j]);
        }
        __syncthreads();
    }

    // epilogue: bias + optional act, scatter by original row ids
#pragma unroll
    for (int j = 0; j < 4; j++) {
        int n = n0 + wn * 32 + j * 8 + 2 * lc;
        float2 bb = *(const float2*)(bias + (long)e * bstride + n);
#pragma unroll
        for (int i = 0; i < 2; i++) {
            int base = wm * 32 + i * 16 + lr;
            int ra = rows[base];
            int rb = rows[base + 8];
            if (ra >= 0) {
                float o0 = c[i][j][0] + bb.x, o1 = c[i][j][1] + bb.y;
                if (ACT == 2) { o0 = act_apply(e, o0); o1 = act_apply(e, o1); }
                *(float2*)(Y + (long)ra * ldy + n) = make_float2(o0, o1);
            }
            if (rb >= 0) {
                float o0 = c[i][j][2] + bb.x, o1 = c[i][j][3] + bb.y;
                if (ACT == 2) { o0 = act_apply(e, o0); o1 = act_apply(e, o1); }
                *(float2*)(Y + (long)rb * ldy + n) = make_float2(o0, o1);
            }
        }
    }
}

// ---------------- softmax + top-8 + route decompose ----------------
__global__ __launch_bounds__(256)
void topk_k(const float* __restrict__ scores, const float* __restrict__ temp,
            int* __restrict__ preE, int* __restrict__ mlpE, int* __restrict__ postE,
            float* __restrict__ wgt, int* __restrict__ cnt)
{
    int t = blockIdx.x;
    __shared__ float s[NCLS];
    __shared__ float rv[256];
    __shared__ int   ri[256];
    __shared__ float selv[TOPK];
    __shared__ int   seli[TOPK];

    int tid = threadIdx.x;
    float invT = 1.0f / temp[0];
    for (int i = tid; i < NCLS; i += 256) s[i] = scores[(long)t * NCLS + i] * invT;
    __syncthreads();

    float m = -INFINITY;
    for (int i = tid; i < NCLS; i += 256) m = fmaxf(m, s[i]);
    rv[tid] = m; __syncthreads();
    for (int o = 128; o > 0; o >>= 1) { if (tid < o) rv[tid] = fmaxf(rv[tid], rv[tid + o]); __syncthreads(); }
    m = rv[0]; __syncthreads();

    float sum = 0.0f;
    for (int i = tid; i < NCLS; i += 256) sum += expf(s[i] - m);
    rv[tid] = sum; __syncthreads();
    for (int o = 128; o > 0; o >>= 1) { if (tid < o) rv[tid] += rv[tid + o]; __syncthreads(); }
    float denom = rv[0]; __syncthreads();

    for (int it = 0; it < TOPK; it++) {
        float bv = -INFINITY; int bi = -1;
        for (int i = tid; i < NCLS; i += 256) {
            bool used = false;
            for (int j = 0; j < it; j++) if (seli[j] == i) used = true;
            if (!used) {
                float v = s[i];
                if (v > bv || (v == bv && (unsigned)i < (unsigned)bi)) { bv = v; bi = i; }
            }
        }
        rv[tid] = bv; ri[tid] = bi; __syncthreads();
        for (int o = 128; o > 0; o >>= 1) {
            if (tid < o) {
                if (rv[tid + o] > rv[tid] ||
                    (rv[tid + o] == rv[tid] && (unsigned)ri[tid + o] < (unsigned)ri[tid])) {
                    rv[tid] = rv[tid + o]; ri[tid] = ri[tid + o];
                }
            }
            __syncthreads();
        }
        if (tid == 0) { selv[it] = rv[0]; seli[it] = ri[0]; }
        __syncthreads();
    }

    if (tid < TOPK) {
        int idx = seli[tid];
        float p = expf(selv[tid] - m) / denom;
        float w = (p >= 1e-6f) ? p : 0.0f;
        int pe = idx >> 8;
        int rem = idx & 255;
        int me = rem >> 4;
        int qe = rem & 15;
        int r = t * TOPK + tid;
        preE[r] = pe; mlpE[r] = me; postE[r] = qe; wgt[r] = w;
        atomicAdd(&cnt[pe], 1);
        atomicAdd(&cnt[16 + me], 1);
        atomicAdd(&cnt[32 + qe], 1);
    }
}

__global__ void zero_k(int* cnt, int* cur) {
    int i = threadIdx.x;
    if (i < 48) { cnt[i] = 0; cur[i] = 0; }
}

__global__ void scan_k(const int* __restrict__ cnt, int* __restrict__ off) {
    if (threadIdx.x == 0) {
        for (int gp = 0; gp < 3; gp++) {
            int a = 0;
            for (int i = 0; i < 16; i++) { off[gp * 17 + i] = a; a += cnt[gp * 16 + i]; }
            off[gp * 17 + 16] = a;
        }
    }
}

__global__ void scatter_k(const int* __restrict__ preE, const int* __restrict__ mlpE,
                          const int* __restrict__ postE, const int* __restrict__ off,
                          int* __restrict__ cur,
                          int* __restrict__ permP, int* __restrict__ permM, int* __restrict__ permQ)
{
    int i = blockIdx.x * blockDim.x + threadIdx.x;
    if (i >= NROWS) return;
    int e, p;
    e = preE[i];  p = off[e]       + atomicAdd(&cur[e],      1); permP[p] = i;
    e = mlpE[i];  p = off[17 + e]  + atomicAdd(&cur[16 + e], 1); permM[p] = i;
    e = postE[i]; p = off[34 + e]  + atomicAdd(&cur[32 + e], 1); permQ[p] = i;
}

// ---------------- row layernorm (+optional act) ----------------
template<int MODE>
__global__ __launch_bounds__(256)
void ln_k(const float* __restrict__ in, float* __restrict__ out,
          const int* __restrict__ eArr, const float* __restrict__ g, const float* __restrict__ be)
{
    int row = blockIdx.x;
    int e = eArr[row];
    const float* xp = in + (long)row * D512;
    float* yp = out + (long)row * D512;
    int tid = threadIdx.x;
    float v0 = xp[tid], v1 = xp[tid + 256];
    if (MODE == 1 && (e & 1)) { yp[tid] = v0; yp[tid + 256] = v1; return; }

    __shared__ float red[256];
    red[tid] = v0 + v1; __syncthreads();
    for (int o = 128; o > 0; o >>= 1) { if (tid < o) red[tid] += red[tid + o]; __syncthreads(); }
    float mu = red[0] * (1.0f / 512.0f);
    __syncthreads();
    float d0 = v0 - mu, d1 = v1 - mu;
    red[tid] = d0 * d0 + d1 * d1; __syncthreads();
    for (int o = 128; o > 0; o >>= 1) { if (tid < o) red[tid] += red[tid + o]; __syncthreads(); }
    float rstd = rsqrtf(red[0] * (1.0f / 512.0f) + 1e-5f);

    float y0 = d0 * rstd * g[e * D512 + tid]       + be[e * D512 + tid];
    float y1 = d1 * rstd * g[e * D512 + tid + 256] + be[e * D512 + tid + 256];
    if (MODE == 0) { y0 = act_apply(e, y0); y1 = act_apply(e, y1); }
    yp[tid] = y0; yp[tid + 256] = y1;
}

// ---------------- weighted combine ----------------
__global__ void final_k(const float* __restrict__ z, const float* __restrict__ wgt,
                        float* __restrict__ out)
{
    int t = blockIdx.x, d = threadIdx.x;
    float acc = 0.0f;
#pragma unroll
    for (int k = 0; k < TOPK; k++) {
        int r = t * TOPK + k;
        acc += wgt[r] * z[(long)r * D512 + d];
    }
    out[(long)t * D512 + d] = acc;
}

// ---------------- launch ----------------
template <typename Tv>
static float* symf(Tv& v) { void* p = nullptr; cudaGetSymbolAddress(&p, v); return (float*)p; }
template <typename Tv>
static int* symi(Tv& v) { void* p = nullptr; cudaGetSymbolAddress(&p, v); return (int*)p; }

extern "C" void kernel_launch(void* const* d_in, const int* in_sizes, int n_in,
                              void* d_out, int out_size)
{
    const float* x      = (const float*)d_in[0];
    const float* r_w1   = (const float*)d_in[1];
    const float* r_b1   = (const float*)d_in[2];
    const float* r_w2   = (const float*)d_in[3];
    const float* r_b2   = (const float*)d_in[4];
    const float* r_w3   = (const float*)d_in[5];
    const float* r_b3   = (const float*)d_in[6];
    const float* temp   = (const float*)d_in[7];
    const float* pre_w  = (const float*)d_in[8];
    const float* pre_b  = (const float*)d_in[9];
    const float* pre_g  = (const float*)d_in[10];
    const float* pre_be = (const float*)d_in[11];
    const float* mlp_w1 = (const float*)d_in[12];
    const float* mlp_b1 = (const float*)d_in[13];
    const float* mlp_w2 = (const float*)d_in[14];
    const float* mlp_b2 = (const float*)d_in[15];
    const float* post_w = (const float*)d_in[16];
    const float* post_b = (const float*)d_in[17];
    const float* post_g = (const float*)d_in[18];
    const float* post_be= (const float*)d_in[19];
    float* out = (float*)d_out;

    float* h1     = symf(g_h1);
    float* h2     = symf(g_h2);
    float* scores = symf(g_scores);
    float* lin    = symf(g_lin);
    float* xin    = symf(g_xin);
    float* hid    = symf(g_hid);
    float* mout   = symf(g_mlpout);
    float* zbuf   = symf(g_z);
    float* wgt    = symf(g_wgt);
    int* preE  = symi(g_preE);
    int* mlpE  = symi(g_mlpE);
    int* postE = symi(g_postE);
    int* cnt   = symi(g_cnt);
    int* cur   = symi(g_cur);
    int* off   = symi(g_off);
    int* permP = symi(g_permP);
    int* permM = symi(g_permM);
    int* permQ = symi(g_permQ);

    // zero first (no deps) — also shifts the ncu capture slot onto the
    // scores GEMM (launch #4) for real roofline data next round.
    zero_k<<<1, 64>>>(cnt, cur);

    // router (fp32 — top-k selection is precision-critical)
    gemm_k<1><<<dim3(4, 8, 1), 256>>>(x, 512, r_w1, 512, r_b1, h1, 512, 256, 512);
    gemm_k<1><<<dim3(2, 8, 1), 256>>>(h1, 512, r_w2, 256, r_b2, h2, 256, 256, 512);
    gemm_k<0><<<dim3(32, 8, 1), 256>>>(h2, 256, r_w3, 4096, r_b3, scores, 4096, 256, 256);

    // routing
    topk_k<<<256, 256>>>(scores, temp, preE, mlpE, postE, wgt, cnt);
    scan_k<<<1, 32>>>(cnt, off);
    scatter_k<<<8, 256>>>(preE, mlpE, postE, off, cur, permP, permM, permQ);

    // pre experts: linear -> LN + act   (tf32 tensor cores, cp.async pipeline)
    gemm_tc<0, 0><<<dim3(4, 32, 16), 256>>>(x, 512, 3, pre_w, 512L * 512, 512, pre_b, 512,
                                            lin, 512, 512, permP, off);
    ln_k<0><<<2048, 256>>>(lin, xin, preE, pre_g, pre_be);

    // mlp experts
    gemm_tc<2, 1><<<dim3(20, 32, 16), 256>>>(xin, 512, 0, mlp_w1, 512L * 2560, 2560, mlp_b1, 2560,
                                             hid, 2560, 512, permM, off + 17);
    gemm_tc<0, 2><<<dim3(4, 32, 16), 256>>>(hid, 2560, 0, mlp_w2, 2560L * 512, 512, mlp_b2, 512,
                                            mout, 512, 0, permM, off + 17);

    // post experts: linear -> optional LN
    gemm_tc<0, 0><<<dim3(4, 32, 16), 256>>>(mout, 512, 0, post_w, 512L * 512, 512, post_b, 512,
                                            lin, 512, 512, permQ, off + 34);
    ln_k<1><<<2048, 256>>>(lin, zbuf, postE, post_g, post_be);

    // weighted combine
    final_k<<<256, 512>>>(zbuf, wgt, out);
    (void)in_sizes; (void)n_in; (void)out_size;
}

// round 10
// speedup vs baseline: 1.5907x; 1.0099x over previous
#include <cuda_runtime.h>
#include <cuda_bf16.h>
#include <math.h>
#include <stdint.h>

// Problem constants
#define D512 512
#define T256 256
#define NROWS 2048          // T * TOPK
#define MAXH 2560
#define NEXP 16
#define NCLS 4096
#define TOPK 8

// ---------------- scratch (device globals; no allocation allowed) ----------
__device__ float g_h1[T256 * D512];
__device__ float g_h2[T256 * 256];
__device__ float g_scores[T256 * NCLS];
__device__ float g_lin[NROWS * D512];
__device__ float g_xin[NROWS * D512];
__device__ float g_hid[NROWS * MAXH];
__device__ float g_mlpout[NROWS * D512];
__device__ float g_z[NROWS * D512];
__device__ int   g_preE[NROWS];
__device__ int   g_mlpE[NROWS];
__device__ int   g_postE[NROWS];
__device__ float g_wgt[NROWS];
__device__ int   g_cnt[48];
__device__ int   g_cur[48];
__device__ int   g_off[51];
__device__ int   g_permP[NROWS];
__device__ int   g_permM[NROWS];
__device__ int   g_permQ[NROWS];

// ---------------- activations ----------------
__device__ __forceinline__ float act_apply(int a, float v) {
    switch (a & 3) {
        case 0:  return 0.5f * v * (1.0f + erff(v * 0.70710678118654752f));
        case 1:  return fmaxf(v, 0.0f);
        case 2:  return tanhf(v);
        default: return v * (1.0f / (1.0f + expf(-v)));
    }
}

__device__ __forceinline__ uint32_t to_tf32_u(float x) {
    uint32_t u;
    asm("cvt.rna.tf32.f32 %0, %1;" : "=r"(u) : "f"(x));
    return u;
}

__device__ __forceinline__ void mma_tf32(float c[4], const uint32_t a[4], const uint32_t b[2]) {
    asm volatile(
        "mma.sync.aligned.m16n8k8.row.col.f32.tf32.tf32.f32 "
        "{%0,%1,%2,%3}, {%4,%5,%6,%7}, {%8,%9}, {%0,%1,%2,%3};"
        : "+f"(c[0]), "+f"(c[1]), "+f"(c[2]), "+f"(c[3])
        : "r"(a[0]), "r"(a[1]), "r"(a[2]), "r"(a[3]), "r"(b[0]), "r"(b[1]));
}

__device__ __forceinline__ void cp16(uint32_t smem_addr, const void* gptr, bool valid) {
    int sz = valid ? 16 : 0;
    asm volatile("cp.async.ca.shared.global [%0], [%1], 16, %2;"
                 :: "r"(smem_addr), "l"(gptr), "r"(sz));
}
__device__ __forceinline__ void cp_commit() {
    asm volatile("cp.async.commit_group;");
}
template<int N>
__device__ __forceinline__ void cp_wait() {
    asm volatile("cp.async.wait_group %0;" :: "n"(N));
}

// ================= fp32 FFMA GEMM (router only: precision-critical) ========
#define BM 32
#define BN 128
#define BK 16

template<int ACT>
__global__ __launch_bounds__(256)
void gemm_k(const float* __restrict__ X, int ldx,
            const float* __restrict__ W, int ldw,
            const float* __restrict__ bias,
            float* __restrict__ Y, int ldy,
            int M, int K)
{
    int n0 = blockIdx.x * BN;
    int m0 = blockIdx.y * BM;
    if (m0 >= M) return;

    __shared__ float Xs[BK][BM];
    __shared__ float Ws[BK][BN];

    int tid = threadIdx.x;
    int tx = tid & 31, ty = tid >> 5;
    int c0 = tx * 4, r0 = ty * 4;

    float acc[4][4];
#pragma unroll
    for (int i = 0; i < 4; i++)
#pragma unroll
        for (int j = 0; j < 4; j++) acc[i][j] = 0.0f;

    int xm = tid >> 2, xk = (tid & 3) * 4;
    const float* xp = X + (long)(m0 + xm) * ldx;
    bool xok = (tid < 128) && (m0 + xm < M);

    for (int k0 = 0; k0 < K; k0 += BK) {
        const float* wp = W + (long)(k0 + ty) * ldw + n0 + c0;
        float4 w0 = *(const float4*)wp;
        float4 w1 = *(const float4*)(wp + (long)8 * ldw);
        float4 xv = make_float4(0.f, 0.f, 0.f, 0.f);
        if (xok) xv = *(const float4*)(xp + k0 + xk);

        *(float4*)&Ws[ty][c0]     = w0;
        *(float4*)&Ws[ty + 8][c0] = w1;
        if (tid < 128) {
            Xs[xk + 0][xm] = xv.x; Xs[xk + 1][xm] = xv.y;
            Xs[xk + 2][xm] = xv.z; Xs[xk + 3][xm] = xv.w;
        }
        __syncthreads();

#pragma unroll
        for (int kk = 0; kk < BK; kk++) {
            float4 a = *(const float4*)&Xs[kk][r0];
            float4 b = *(const float4*)&Ws[kk][c0];
            acc[0][0] += a.x * b.x; acc[0][1] += a.x * b.y; acc[0][2] += a.x * b.z; acc[0][3] += a.x * b.w;
            acc[1][0] += a.y * b.x; acc[1][1] += a.y * b.y; acc[1][2] += a.y * b.z; acc[1][3] += a.y * b.w;
            acc[2][0] += a.z * b.x; acc[2][1] += a.z * b.y; acc[2][2] += a.z * b.z; acc[2][3] += a.z * b.w;
            acc[3][0] += a.w * b.x; acc[3][1] += a.w * b.y; acc[3][2] += a.w * b.z; acc[3][3] += a.w * b.w;
        }
        __syncthreads();
    }

    float4 bb = *(const float4*)(bias + n0 + c0);
#pragma unroll
    for (int i = 0; i < 4; i++) {
        int r = m0 + r0 + i;
        if (r >= M) continue;
        float4 o;
        o.x = acc[i][0] + bb.x; o.y = acc[i][1] + bb.y;
        o.z = acc[i][2] + bb.z; o.w = acc[i][3] + bb.w;
        if (ACT == 1) {
            o.x = act_apply(0, o.x); o.y = act_apply(0, o.y);
            o.z = act_apply(0, o.z); o.w = act_apply(0, o.w);
        }
        *(float4*)(Y + (long)r * ldy + n0 + c0) = o;
    }
}

// ===== tf32 tensor-core grouped GEMM, 4-stage cp.async, single-sync loop ===
// BM=64, BN=128, BK=16; 8 warps, each 32x32 via m16n8k8 tf32 mma.sync.
// Dynamic smem (62.7 KB): Xs[4][64][28] | Ws[4][16][132] | rows[64]
#define STAGES 4
#define XPAD 28
#define WPAD 132
#define XS_SZ (64 * XPAD)
#define WS_SZ (16 * WPAD)
#define TC_SMEM_BYTES (STAGES * (XS_SZ + WS_SZ) * (int)sizeof(float) + 64 * (int)sizeof(int))

template<int ACT, int NKMODE>
__global__ __launch_bounds__(256)
void gemm_tc(const float* __restrict__ X, int ldx, int xshift,
             const float* __restrict__ W, long wstride, int ldw,
             const float* __restrict__ bias, int bstride,
             float* __restrict__ Y, int ldy,
             int K,
             const int* __restrict__ perm, const int* __restrict__ segoff)
{
    int e  = blockIdx.z;
    int n0 = blockIdx.x * 128;
    int he = 512 * (2 + (e >> 2));
    if (NKMODE == 1 && n0 >= he) return;
    int Keff = (NKMODE == 2) ? he : K;

    int segs = segoff[e], sege = segoff[e + 1];
    int m0 = segs + blockIdx.y * 64;
    if (m0 >= sege) return;

    extern __shared__ float sm[];
    float* XsB = sm;                               // STAGES * XS_SZ
    float* WsB = sm + STAGES * XS_SZ;              // STAGES * WS_SZ
    int*   rows = (int*)(sm + STAGES * (XS_SZ + WS_SZ));

    int tid = threadIdx.x;
    if (tid < 64) {
        int p = m0 + tid;
        rows[tid] = (p < sege) ? perm[p] : -1;
    }
    __syncthreads();

    const float* Wb = W + (long)e * wstride;

    // loader mapping
    int wrow = tid >> 5, wc4 = (tid & 31) * 4;   // W: rows wrow, wrow+8
    int xrow = tid >> 2, xc4 = (tid & 3) * 4;    // X: 64 rows x 16 cols
    int xr = rows[xrow];
    const float* xp = X + (long)((xr >= 0 ? xr : 0) >> xshift) * ldx;
    bool xok = (xr >= 0);

    uint32_t xs_dst[STAGES], ws_dst0[STAGES], ws_dst1[STAGES];
#pragma unroll
    for (int s = 0; s < STAGES; s++) {
        xs_dst[s]  = (uint32_t)__cvta_generic_to_shared(&XsB[s * XS_SZ + xrow * XPAD + xc4]);
        ws_dst0[s] = (uint32_t)__cvta_generic_to_shared(&WsB[s * WS_SZ + wrow * WPAD + wc4]);
        ws_dst1[s] = (uint32_t)__cvta_generic_to_shared(&WsB[s * WS_SZ + (wrow + 8) * WPAD + wc4]);
    }

    int nk = Keff >> 4;

    // prologue: issue stages 0..STAGES-2
#pragma unroll
    for (int s = 0; s < STAGES - 1; s++) {
        if (s < nk) {
            int k0 = s << 4;
            cp16(ws_dst0[s], Wb + (long)(k0 + wrow) * ldw + n0 + wc4, true);
            cp16(ws_dst1[s], Wb + (long)(k0 + wrow + 8) * ldw + n0 + wc4, true);
            cp16(xs_dst[s],  xp + k0 + xc4, xok);
        }
        cp_commit();
    }

    int lane = tid & 31, warp = tid >> 5;
    int wm = warp >> 2, wn = warp & 3;
    int lr = lane >> 2, lc = lane & 3;

    float c[2][4][4];
#pragma unroll
    for (int i = 0; i < 2; i++)
#pragma unroll
        for (int j = 0; j < 4; j++)
#pragma unroll
            for (int q = 0; q < 4; q++) c[i][j][q] = 0.0f;

    for (int t = 0; t < nk; t++) {
        // own-thread wait for tile t, then barrier for cross-warp visibility.
        // The barrier ALSO guarantees all warps finished reading the buffer
        // that this iteration's cp.async overwrites ((t+STAGES-1)%STAGES ==
        // (t-1)%STAGES, last read in iter t-1) — so no trailing sync needed.
        cp_wait<STAGES - 2>();
        __syncthreads();

        int tn = t + STAGES - 1;
        if (tn < nk) {
            int k0 = tn << 4;
            int s = tn % STAGES;
            cp16(ws_dst0[s], Wb + (long)(k0 + wrow) * ldw + n0 + wc4, true);
            cp16(ws_dst1[s], Wb + (long)(k0 + wrow + 8) * ldw + n0 + wc4, true);
            cp16(xs_dst[s],  xp + k0 + xc4, xok);
        }
        cp_commit();

        int buf = t % STAGES;
        const float* Xb = XsB + buf * XS_SZ;
        const float* Wv = WsB + buf * WS_SZ;
#pragma unroll
        for (int ks = 0; ks < 16; ks += 8) {
            uint32_t a[2][4], b[4][2];
#pragma unroll
            for (int i = 0; i < 2; i++) {
                int bm = wm * 32 + i * 16;
                a[i][0] = to_tf32_u(Xb[(bm + lr    ) * XPAD + ks + lc    ]);
                a[i][1] = to_tf32_u(Xb[(bm + lr + 8) * XPAD + ks + lc    ]);
                a[i][2] = to_tf32_u(Xb[(bm + lr    ) * XPAD + ks + lc + 4]);
                a[i][3] = to_tf32_u(Xb[(bm + lr + 8) * XPAD + ks + lc + 4]);
            }
#pragma unroll
            for (int j = 0; j < 4; j++) {
                int bn = wn * 32 + j * 8 + lr;
                b[j][0] = to_tf32_u(Wv[(ks + lc    ) * WPAD + bn]);
                b[j][1] = to_tf32_u(Wv[(ks + lc + 4) * WPAD + bn]);
            }
#pragma unroll
            for (int i = 0; i < 2; i++)
#pragma unroll
                for (int j = 0; j < 4; j++)
                    mma_tf32(c[i][j], a[i], b[j]);
        }
        // no trailing __syncthreads (see comment above)
    }

    // epilogue: bias + optional act, scatter by original row ids
#pragma unroll
    for (int j = 0; j < 4; j++) {
        int n = n0 + wn * 32 + j * 8 + 2 * lc;
        float2 bb = *(const float2*)(bias + (long)e * bstride + n);
#pragma unroll
        for (int i = 0; i < 2; i++) {
            int base = wm * 32 + i * 16 + lr;
            int ra = rows[base];
            int rb = rows[base + 8];
            if (ra >= 0) {
                float o0 = c[i][j][0] + bb.x, o1 = c[i][j][1] + bb.y;
                if (ACT == 2) { o0 = act_apply(e, o0); o1 = act_apply(e, o1); }
                *(float2*)(Y + (long)ra * ldy + n) = make_float2(o0, o1);
            }
            if (rb >= 0) {
                float o0 = c[i][j][2] + bb.x, o1 = c[i][j][3] + bb.y;
                if (ACT == 2) { o0 = act_apply(e, o0); o1 = act_apply(e, o1); }
                *(float2*)(Y + (long)rb * ldy + n) = make_float2(o0, o1);
            }
        }
    }
}

// ---------------- softmax + top-8 + route decompose ----------------
__global__ __launch_bounds__(256)
void topk_k(const float* __restrict__ scores, const float* __restrict__ temp,
            int* __restrict__ preE, int* __restrict__ mlpE, int* __restrict__ postE,
            float* __restrict__ wgt, int* __restrict__ cnt)
{
    int t = blockIdx.x;
    __shared__ float s[NCLS];
    __shared__ float rv[256];
    __shared__ int   ri[256];
    __shared__ float selv[TOPK];
    __shared__ int   seli[TOPK];

    int tid = threadIdx.x;
    float invT = 1.0f / temp[0];
    for (int i = tid; i < NCLS; i += 256) s[i] = scores[(long)t * NCLS + i] * invT;
    __syncthreads();

    float m = -INFINITY;
    for (int i = tid; i < NCLS; i += 256) m = fmaxf(m, s[i]);
    rv[tid] = m; __syncthreads();
    for (int o = 128; o > 0; o >>= 1) { if (tid < o) rv[tid] = fmaxf(rv[tid], rv[tid + o]); __syncthreads(); }
    m = rv[0]; __syncthreads();

    float sum = 0.0f;
    for (int i = tid; i < NCLS; i += 256) sum += expf(s[i] - m);
    rv[tid] = sum; __syncthreads();
    for (int o = 128; o > 0; o >>= 1) { if (tid < o) rv[tid] += rv[tid + o]; __syncthreads(); }
    float denom = rv[0]; __syncthreads();

    for (int it = 0; it < TOPK; it++) {
        float bv = -INFINITY; int bi = -1;
        for (int i = tid; i < NCLS; i += 256) {
            bool used = false;
            for (int j = 0; j < it; j++) if (seli[j] == i) used = true;
            if (!used) {
                float v = s[i];
                if (v > bv || (v == bv && (unsigned)i < (unsigned)bi)) { bv = v; bi = i; }
            }
        }
        rv[tid] = bv; ri[tid] = bi; __syncthreads();
        for (int o = 128; o > 0; o >>= 1) {
            if (tid < o) {
                if (rv[tid + o] > rv[tid] ||
                    (rv[tid + o] == rv[tid] && (unsigned)ri[tid + o] < (unsigned)ri[tid])) {
                    rv[tid] = rv[tid + o]; ri[tid] = ri[tid + o];
                }
            }
            __syncthreads();
        }
        if (tid == 0) { selv[it] = rv[0]; seli[it] = ri[0]; }
        __syncthreads();
    }

    if (tid < TOPK) {
        int idx = seli[tid];
        float p = expf(selv[tid] - m) / denom;
        float w = (p >= 1e-6f) ? p : 0.0f;
        int pe = idx >> 8;
        int rem = idx & 255;
        int me = rem >> 4;
        int qe = rem & 15;
        int r = t * TOPK + tid;
        preE[r] = pe; mlpE[r] = me; postE[r] = qe; wgt[r] = w;
        atomicAdd(&cnt[pe], 1);
        atomicAdd(&cnt[16 + me], 1);
        atomicAdd(&cnt[32 + qe], 1);
    }
}

__global__ void zero_k(int* cnt, int* cur) {
    int i = threadIdx.x;
    if (i < 48) { cnt[i] = 0; cur[i] = 0; }
}

__global__ void scan_k(const int* __restrict__ cnt, int* __restrict__ off) {
    if (threadIdx.x == 0) {
        for (int gp = 0; gp < 3; gp++) {
            int a = 0;
            for (int i = 0; i < 16; i++) { off[gp * 17 + i] = a; a += cnt[gp * 16 + i]; }
            off[gp * 17 + 16] = a;
        }
    }
}

__global__ void scatter_k(const int* __restrict__ preE, const int* __restrict__ mlpE,
                          const int* __restrict__ postE, const int* __restrict__ off,
                          int* __restrict__ cur,
                          int* __restrict__ permP, int* __restrict__ permM, int* __restrict__ permQ)
{
    int i = blockIdx.x * blockDim.x + threadIdx.x;
    if (i >= NROWS) return;
    int e, p;
    e = preE[i];  p = off[e]       + atomicAdd(&cur[e],      1); permP[p] = i;
    e = mlpE[i];  p = off[17 + e]  + atomicAdd(&cur[16 + e], 1); permM[p] = i;
    e = postE[i]; p = off[34 + e]  + atomicAdd(&cur[32 + e], 1); permQ[p] = i;
}

// ---------------- row layernorm (+optional act) ----------------
template<int MODE>
__global__ __launch_bounds__(256)
void ln_k(const float* __restrict__ in, float* __restrict__ out,
          const int* __restrict__ eArr, const float* __restrict__ g, const float* __restrict__ be)
{
    int row = blockIdx.x;
    int e = eArr[row];
    const float* xp = in + (long)row * D512;
    float* yp = out + (long)row * D512;
    int tid = threadIdx.x;
    float v0 = xp[tid], v1 = xp[tid + 256];
    if (MODE == 1 && (e & 1)) { yp[tid] = v0; yp[tid + 256] = v1; return; }

    __shared__ float red[256];
    red[tid] = v0 + v1; __syncthreads();
    for (int o = 128; o > 0; o >>= 1) { if (tid < o) red[tid] += red[tid + o]; __syncthreads(); }
    float mu = red[0] * (1.0f / 512.0f);
    __syncthreads();
    float d0 = v0 - mu, d1 = v1 - mu;
    red[tid] = d0 * d0 + d1 * d1; __syncthreads();
    for (int o = 128; o > 0; o >>= 1) { if (tid < o) red[tid] += red[tid + o]; __syncthreads(); }
    float rstd = rsqrtf(red[0] * (1.0f / 512.0f) + 1e-5f);

    float y0 = d0 * rstd * g[e * D512 + tid]       + be[e * D512 + tid];
    float y1 = d1 * rstd * g[e * D512 + tid + 256] + be[e * D512 + tid + 256];
    if (MODE == 0) { y0 = act_apply(e, y0); y1 = act_apply(e, y1); }
    yp[tid] = y0; yp[tid + 256] = y1;
}

// ---------------- weighted combine ----------------
__global__ void final_k(const float* __restrict__ z, const float* __restrict__ wgt,
                        float* __restrict__ out)
{
    int t = blockIdx.x, d = threadIdx.x;
    float acc = 0.0f;
#pragma unroll
    for (int k = 0; k < TOPK; k++) {
        int r = t * TOPK + k;
        acc += wgt[r] * z[(long)r * D512 + d];
    }
    out[(long)t * D512 + d] = acc;
}

// ---------------- launch ----------------
template <typename Tv>
static float* symf(Tv& v) { void* p = nullptr; cudaGetSymbolAddress(&p, v); return (float*)p; }
template <typename Tv>
static int* symi(Tv& v) { void* p = nullptr; cudaGetSymbolAddress(&p, v); return (int*)p; }

extern "C" void kernel_launch(void* const* d_in, const int* in_sizes, int n_in,
                              void* d_out, int out_size)
{
    const float* x      = (const float*)d_in[0];
    const float* r_w1   = (const float*)d_in[1];
    const float* r_b1   = (const float*)d_in[2];
    const float* r_w2   = (const float*)d_in[3];
    const float* r_b2   = (const float*)d_in[4];
    const float* r_w3   = (const float*)d_in[5];
    const float* r_b3   = (const float*)d_in[6];
    const float* temp   = (const float*)d_in[7];
    const float* pre_w  = (const float*)d_in[8];
    const float* pre_b  = (const float*)d_in[9];
    const float* pre_g  = (const float*)d_in[10];
    const float* pre_be = (const float*)d_in[11];
    const float* mlp_w1 = (const float*)d_in[12];
    const float* mlp_b1 = (const float*)d_in[13];
    const float* mlp_w2 = (const float*)d_in[14];
    const float* mlp_b2 = (const float*)d_in[15];
    const float* post_w = (const float*)d_in[16];
    const float* post_b = (const float*)d_in[17];
    const float* post_g = (const float*)d_in[18];
    const float* post_be= (const float*)d_in[19];
    float* out = (float*)d_out;

    float* h1     = symf(g_h1);
    float* h2     = symf(g_h2);
    float* scores = symf(g_scores);
    float* lin    = symf(g_lin);
    float* xin    = symf(g_xin);
    float* hid    = symf(g_hid);
    float* mout   = symf(g_mlpout);
    float* zbuf   = symf(g_z);
    float* wgt    = symf(g_wgt);
    int* preE  = symi(g_preE);
    int* mlpE  = symi(g_mlpE);
    int* postE = symi(g_postE);
    int* cnt   = symi(g_cnt);
    int* cur   = symi(g_cur);
    int* off   = symi(g_off);
    int* permP = symi(g_permP);
    int* permM = symi(g_permM);
    int* permQ = symi(g_permQ);

    // allow >48KB dynamic smem for the pipelined GEMMs (attribute set is
    // not a stream op — capture-safe; idempotent)
    cudaFuncSetAttribute(gemm_tc<0, 0>, cudaFuncAttributeMaxDynamicSharedMemorySize, TC_SMEM_BYTES);
    cudaFuncSetAttribute(gemm_tc<2, 1>, cudaFuncAttributeMaxDynamicSharedMemorySize, TC_SMEM_BYTES);
    cudaFuncSetAttribute(gemm_tc<0, 2>, cudaFuncAttributeMaxDynamicSharedMemorySize, TC_SMEM_BYTES);

    // zero first (no deps) — keeps the scores GEMM in the ncu capture slot.
    zero_k<<<1, 64>>>(cnt, cur);

    // router (fp32 — top-k selection is precision-critical)
    gemm_k<1><<<dim3(4, 8, 1), 256>>>(x, 512, r_w1, 512, r_b1, h1, 512, 256, 512);
    gemm_k<1><<<dim3(2, 8, 1), 256>>>(h1, 512, r_w2, 256, r_b2, h2, 256, 256, 512);
    gemm_k<0><<<dim3(32, 8, 1), 256>>>(h2, 256, r_w3, 4096, r_b3, scores, 4096, 256, 256);

    // routing
    topk_k<<<256, 256>>>(scores, temp, preE, mlpE, postE, wgt, cnt);
    scan_k<<<1, 32>>>(cnt, off);
    scatter_k<<<8, 256>>>(preE, mlpE, postE, off, cur, permP, permM, permQ);

    // pre experts: linear -> LN + act   (tf32 tensor cores, 4-stage pipeline)
    gemm_tc<0, 0><<<dim3(4, 32, 16), 256, TC_SMEM_BYTES>>>(
        x, 512, 3, pre_w, 512L * 512, 512, pre_b, 512, lin, 512, 512, permP, off);
    ln_k<0><<<2048, 256>>>(lin, xin, preE, pre_g, pre_be);

    // mlp experts
    gemm_tc<2, 1><<<dim3(20, 32, 16), 256, TC_SMEM_BYTES>>>(
        xin, 512, 0, mlp_w1, 512L * 2560, 2560, mlp_b1, 2560, hid, 2560, 512, permM, off + 17);
    gemm_tc<0, 2><<<dim3(4, 32, 16), 256, TC_SMEM_BYTES>>>(
        hid, 2560, 0, mlp_w2, 2560L * 512, 512, mlp_b2, 512, mout, 512, 0, permM, off + 17);

    // post experts: linear -> optional LN
    gemm_tc<0, 0><<<dim3(4, 32, 16), 256, TC_SMEM_BYTES>>>(
        mout, 512, 0, post_w, 512L * 512, 512, post_b, 512, lin, 512, 512, permQ, off + 34);
    ln_k<1><<<2048, 256>>>(lin, zbuf, postE, post_g, post_be);

    // weighted combine
    final_k<<<256, 512>>>(zbuf, wgt, out);
    (void)in_sizes; (void)n_in; (void)out_size;
}